// round 2
// baseline (speedup 1.0000x reference)
#include <cuda_runtime.h>
#include <cuda_bf16.h>

// BrockHommes sequential scan, lag-4 dependence => 4-way parallel groups.
// Lanes 0..3 each compute one timestep of the current group of 4; window
// state exchanged with exactly TWO shfl.idx per group via select-publish.
// Softmax shifted by e0 (q0==1): no max tree, 3 raw EX2 ops.
// Division = MUFU.RCP + FMA, with eps*sigma/R precomputed off-chain.

#define BH_MASK 0x0000000Fu

__device__ __forceinline__ float ex2a(float x) {
    float r; asm("ex2.approx.ftz.f32 %0, %1;" : "=f"(r) : "f"(x)); return r;
}
__device__ __forceinline__ float rcpa(float x) {
    float r; asm("rcp.approx.ftz.f32 %0, %1;" : "=f"(r) : "f"(x)); return r;
}

__global__ void __launch_bounds__(32, 1) bh_scan_kernel(
    const float* __restrict__ params,
    const float* __restrict__ eps,
    float* __restrict__ out,
    int n)
{
    const int lane = (int)threadIdx.x;
    if (lane >= 4) return;

    // --- derived parameters (uniform across lanes) ---
    const float beta  = expf(params[0]);
    const float sigma = expf(params[9]);          // params[-2]
    const float R     = 1.0f + expf(params[10]);  // params[-1]
    const float Rinv  = 1.0f / R;
    const float sigR  = sigma * Rinv;             // eps multiplier, off-chain
    const float beta2 = beta * 1.44269504088896340736f;  // beta * log2(e)

    const float g0 = params[1], g1 = params[2], g2 = params[3], g3 = params[4];
    const float b0 = params[5], b1 = params[6], b2 = params[7], b3 = params[8];

    // exponent diffs vs branch 0, with beta*log2e folded in:
    // d_i = (p4 - R*p5) * (bdg_i * p6 + bdb_i)
    const float bdg1 = beta2 * (g1 - g0), bdb1 = beta2 * (b1 - b0);
    const float bdg2 = beta2 * (g2 - g0), bdb2 = beta2 * (b2 - b0);
    const float bdg3 = beta2 * (g3 - g0), bdb3 = beta2 * (b3 - b0);

    // shuffle sources + publish predicates (loop-invariant)
    const int  srcA = (lane + 3) & 3;   // p5 source
    const int  srcB = (lane + 2) & 3;   // p6 source
    const bool is3  = (lane == 3);
    const bool hi2  = (lane >= 2);

    // per-lane window for t = 4*grp + lane: p4=x_{t-4}, p5=x_{t-5}, p6=x_{t-6}
    float p4 = 0.0f, p5 = 0.0f, p6 = 0.0f;

    const int ngroups = n >> 2;
    int t = lane;
    // depth-2 epsilon prefetch (streaming; keeps LDG latency off the chain)
    float eA = (t     < n) ? eps[t]     : 0.0f;
    float eB = (t + 4 < n) ? eps[t + 4] : 0.0f;

    #pragma unroll 2
    for (int grp = 0; grp < ngroups; ++grp, t += 4) {
        const float es = eA * sigR;                    // eps*sigma/R, off-chain
        eA = eB;
        if (t + 8 < n) eB = eps[t + 8];

        // --- critical chain ---
        const float rx5 = R * p5;
        const float am  = p4 - rx5;                    // (xm4 - R*xm5)
        const float c1  = fmaf(bdg1, p6, bdb1);        // parallel w/ rx5 chain
        const float c2  = fmaf(bdg2, p6, bdb2);
        const float c3  = fmaf(bdg3, p6, bdb3);
        const float q1  = ex2a(am * c1);
        const float q2  = ex2a(am * c2);
        const float q3  = ex2a(am * c3);               // q0 == 1

        const float y0 = fmaf(g0, p4, b0);
        const float y1 = fmaf(g1, p4, b1);
        const float y2 = fmaf(g2, p4, b2);
        const float y3 = fmaf(g3, p4, b3);

        const float S0 = (q1 + q2) + (q3 + 1.0f);
        const float S1 = fmaf(q1, y1, y0) + fmaf(q3, y3, q2 * y2);

        // x = (S1/S0)/R + eps*sigma/R ; RCP overlaps the S1*Rinv multiply
        const float r0  = rcpa(S0);
        const float S1R = S1 * Rinv;
        const float x   = fmaf(S1R, r0, es);

        out[t] = x;

        // --- window update: 2 shuffles via select-publish ---
        const float u = is3 ? p4 : x;   // -> p5_new at reader (lane+? ) side
        const float v = hi2 ? p4 : x;   // -> p6_new
        p5 = __shfl_sync(BH_MASK, u, srcA);
        p6 = __shfl_sync(BH_MASK, v, srcB);
        p4 = x;
    }

    // tail (n % 4 leftover steps) — independent of each other (lag >= 4)
    const int rem = n & 3;
    if (lane < rem) {
        const int tt = 4 * ngroups + lane;
        const float es  = eps[tt] * sigR;
        const float rx5 = R * p5;
        const float am  = p4 - rx5;
        const float q1  = ex2a(am * fmaf(bdg1, p6, bdb1));
        const float q2  = ex2a(am * fmaf(bdg2, p6, bdb2));
        const float q3  = ex2a(am * fmaf(bdg3, p6, bdb3));
        const float y0 = fmaf(g0, p4, b0);
        const float y1 = fmaf(g1, p4, b1);
        const float y2 = fmaf(g2, p4, b2);
        const float y3 = fmaf(g3, p4, b3);
        const float S0 = (q1 + q2) + (q3 + 1.0f);
        const float S1 = fmaf(q1, y1, y0) + fmaf(q3, y3, q2 * y2);
        out[tt] = fmaf(S1 * Rinv, rcpa(S0), es);
    }
}

extern "C" void kernel_launch(void* const* d_in, const int* in_sizes, int n_in,
                              void* d_out, int out_size)
{
    const float* params = (const float*)d_in[0];
    const float* eps    = (const float*)d_in[1];
    float* out          = (float*)d_out;
    const int n = in_sizes[1];

    bh_scan_kernel<<<1, 32>>>(params, eps, out, n);
}

// round 3
// speedup vs baseline: 2.0983x; 2.0983x over previous
#include <cuda_runtime.h>
#include <cuda_bf16.h>

// BrockHommes sequential scan, lag-4 dependence => 4-way parallel groups.
// All 32 lanes stay converged: the 4-lane computation is replicated across
// 8 quads via width-4 shuffles (no divergence => no WARPSYNC on the chain).
// Only lanes 0-3 commit stores. Softmax shifted by branch 0 (q0==1),
// raw EX2/RCP MUFU ops, division-free epilogue, depth-2 eps prefetch.

__device__ __forceinline__ float ex2a(float x) {
    float r; asm("ex2.approx.ftz.f32 %0, %1;" : "=f"(r) : "f"(x)); return r;
}
__device__ __forceinline__ float rcpa(float x) {
    float r; asm("rcp.approx.ftz.f32 %0, %1;" : "=f"(r) : "f"(x)); return r;
}

__global__ void __launch_bounds__(32, 1) bh_scan_kernel(
    const float* __restrict__ params,
    const float* __restrict__ eps,
    float* __restrict__ out,
    int n)
{
    const int lane = (int)threadIdx.x;
    const int lq   = lane & 3;            // lane within quad (replicated x8)

    // --- derived parameters (uniform) ---
    const float beta  = expf(params[0]);
    const float sigma = expf(params[9]);          // params[-2]
    const float R     = 1.0f + expf(params[10]);  // params[-1]
    const float negR  = -R;
    const float Rinv  = 1.0f / R;
    const float sigR  = sigma * Rinv;
    const float beta2 = beta * 1.44269504088896340736f;  // beta * log2(e)

    const float g0 = params[1], g1 = params[2], g2 = params[3], g3 = params[4];
    const float b0 = params[5], b1 = params[6], b2 = params[7], b3 = params[8];

    // exponent diffs vs branch 0 (beta*log2e folded):
    const float bdg1 = beta2 * (g1 - g0), bdb1 = beta2 * (b1 - b0);
    const float bdg2 = beta2 * (g2 - g0), bdb2 = beta2 * (b2 - b0);
    const float bdg3 = beta2 * (g3 - g0), bdb3 = beta2 * (b3 - b0);

    const int  srcA = (lq + 3) & 3;   // p5 source within quad
    const int  srcB = (lq + 2) & 3;   // p6 source within quad
    const bool is3  = (lq == 3);
    const bool hi2  = (lq >= 2);
    const bool wr   = (lane < 4);     // only quad 0 commits stores

    // window for t = 4*grp + lq: p4=x_{t-4}, p5=x_{t-5}, p6=x_{t-6}
    float p4 = 0.0f, p5 = 0.0f, p6 = 0.0f;

    const int ngroups = n >> 2;
    const int nmain   = (ngroups > 2) ? (ngroups - 2) : 0;
    int t = lq;
    float eA = (t     < n) ? eps[t]     : 0.0f;
    float eB = (t + 4 < n) ? eps[t + 4] : 0.0f;

    // main loop: prefetch provably in-bounds (t+8 <= 4*(nmain-1)+3+8 < 4*ngroups <= n)
    #pragma unroll 4
    for (int grp = 0; grp < nmain; ++grp, t += 4) {
        const float es = eA * sigR;        // off-chain
        eA = eB;
        eB = eps[t + 8];                   // unconditional prefetch

        // --- critical chain ---
        const float am = fmaf(negR, p5, p4);          // xm4 - R*xm5 (1 FMA)
        const float c1 = fmaf(bdg1, p6, bdb1);
        const float c2 = fmaf(bdg2, p6, bdb2);
        const float c3 = fmaf(bdg3, p6, bdb3);
        const float q1 = ex2a(am * c1);
        const float q2 = ex2a(am * c2);
        const float q3 = ex2a(am * c3);               // issued last -> ready last

        const float y0 = fmaf(g0, p4, b0);
        const float y1 = fmaf(g1, p4, b1);
        const float y2 = fmaf(g2, p4, b2);
        const float y3 = fmaf(g3, p4, b3);

        // last-ready q3 feeds the shallowest tree position
        const float S0 = ((q1 + q2) + 1.0f) + q3;
        float s = fmaf(q1, y1, y0);
        s = fmaf(q2, y2, s);
        const float S1 = fmaf(q3, y3, s);

        const float r0  = rcpa(S0);
        const float S1R = S1 * Rinv;
        const float x   = fmaf(S1R, r0, es);

        if (wr) out[t] = x;                // predicated STG, no branch

        // --- window update: 2 width-4 shuffles, fully converged warp ---
        const float u = is3 ? p4 : x;
        const float v = hi2 ? p4 : x;
        p5 = __shfl_sync(0xFFFFFFFFu, u, srcA, 4);
        p6 = __shfl_sync(0xFFFFFFFFu, v, srcB, 4);
        p4 = x;
    }

    // last (up to 2) full groups: guarded prefetch
    for (int grp = nmain; grp < ngroups; ++grp, t += 4) {
        const float es = eA * sigR;
        eA = eB;
        eB = (t + 8 < n) ? eps[t + 8] : 0.0f;

        const float am = fmaf(negR, p5, p4);
        const float c1 = fmaf(bdg1, p6, bdb1);
        const float c2 = fmaf(bdg2, p6, bdb2);
        const float c3 = fmaf(bdg3, p6, bdb3);
        const float q1 = ex2a(am * c1);
        const float q2 = ex2a(am * c2);
        const float q3 = ex2a(am * c3);
        const float y0 = fmaf(g0, p4, b0);
        const float y1 = fmaf(g1, p4, b1);
        const float y2 = fmaf(g2, p4, b2);
        const float y3 = fmaf(g3, p4, b3);
        const float S0 = ((q1 + q2) + 1.0f) + q3;
        float s = fmaf(q1, y1, y0);
        s = fmaf(q2, y2, s);
        const float S1 = fmaf(q3, y3, s);
        const float x  = fmaf(S1 * Rinv, rcpa(S0), es);

        if (wr) out[t] = x;

        const float u = is3 ? p4 : x;
        const float v = hi2 ? p4 : x;
        p5 = __shfl_sync(0xFFFFFFFFu, u, srcA, 4);
        p6 = __shfl_sync(0xFFFFFFFFu, v, srcB, 4);
        p4 = x;
    }

    // remainder steps (n % 4), mutually independent (lag >= 4)
    const int rem = n & 3;
    if (rem) {
        const int tt = 4 * ngroups + lq;
        if (lane < rem) {
            const float es = eps[tt] * sigR;
            const float am = fmaf(negR, p5, p4);
            const float q1 = ex2a(am * fmaf(bdg1, p6, bdb1));
            const float q2 = ex2a(am * fmaf(bdg2, p6, bdb2));
            const float q3 = ex2a(am * fmaf(bdg3, p6, bdb3));
            const float y0 = fmaf(g0, p4, b0);
            const float y1 = fmaf(g1, p4, b1);
            const float y2 = fmaf(g2, p4, b2);
            const float y3 = fmaf(g3, p4, b3);
            const float S0 = ((q1 + q2) + 1.0f) + q3;
            float s = fmaf(q1, y1, y0);
            s = fmaf(q2, y2, s);
            const float S1 = fmaf(q3, y3, s);
            out[tt] = fmaf(S1 * Rinv, rcpa(S0), es);
        }
    }
}

extern "C" void kernel_launch(void* const* d_in, const int* in_sizes, int n_in,
                              void* d_out, int out_size)
{
    const float* params = (const float*)d_in[0];
    const float* eps    = (const float*)d_in[1];
    float* out          = (float*)d_out;
    const int n = in_sizes[1];

    bh_scan_kernel<<<1, 32>>>(params, eps, out, n);
}